// round 13
// baseline (speedup 1.0000x reference)
#include <cuda_runtime.h>
#include <cuda_bf16.h>
#include <math_constants.h>

// Problem constants (fixed by the dataset)
#define NN 50000
#define NE 800000
#define ETOT (NE + NN)       // edges + self loops = 850000
#define NG 64
#define HEADS 4
#define NSUB 8               // GraphNorm sub-partitions per graph

// ---------------- scratch (no cudaMalloc allowed) ----------------
__device__ float g_xl[NN * 128];
__device__ float g_xr[NN * 128];
__device__ float g_h1[NN * 128];
__device__ float g_h2[NN * 64];
__device__ float g_h3[NN * 8];
__device__ int   g_deg[NN];      // zero-init at load; re-zeroed inside scan each call
__device__ int   g_off[NN + 1];
__device__ int   g_rank[ETOT];   // per-edge arrival rank at its dst
__device__ int   g_srcs[ETOT];
__device__ int   g_go[NG + 1];
__device__ float g_part[NG * NSUB * 2 * 128];
__device__ float g_mus[NG * 128];
__device__ float g_wr[NG * 128];

// packed bf16x2 hi/lo weight buffers (k-pairs x M), all 6 matrices
#define OFF_L1_0 0
#define OFF_L1_1 8192
#define OFF_L2_0 16384
#define OFF_L2_1 20480
#define OFF_L3_0 24576
#define OFF_L3_1 25600
#define BTOT 26624
__device__ unsigned g_bh[BTOT];
__device__ unsigned g_bl[BTOT];

// ---------------- cp.async helpers ----------------
__device__ __forceinline__ void cp_async16(void* smem_ptr, const void* gmem_ptr, bool pred) {
    unsigned saddr = (unsigned)__cvta_generic_to_shared(smem_ptr);
    int sz = pred ? 16 : 0;
    asm volatile("cp.async.ca.shared.global [%0], [%1], 16, %2;\n"
                 :: "r"(saddr), "l"(gmem_ptr), "r"(sz));
}
__device__ __forceinline__ void cp_commit() { asm volatile("cp.async.commit_group;\n"); }
template <int N>
__device__ __forceinline__ void cp_wait() { asm volatile("cp.async.wait_group %0;\n" :: "n"(N)); }

// ---------------- bf16 split helpers ----------------
__device__ __forceinline__ void split_bf16x2(float v0, float v1, unsigned& hi, unsigned& lo) {
    asm("cvt.rn.bf16x2.f32 %0, %1, %2;" : "=r"(hi) : "f"(v1), "f"(v0));
    float f0 = __uint_as_float(hi << 16);
    float f1 = __uint_as_float(hi & 0xffff0000u);
    asm("cvt.rn.bf16x2.f32 %0, %1, %2;" : "=r"(lo) : "f"(v1 - f1), "f"(v0 - f0));
}

__device__ __forceinline__ void mma_bf16(float c[4], unsigned a0, unsigned a1,
                                         unsigned a2, unsigned a3,
                                         unsigned b0, unsigned b1) {
    asm volatile(
        "mma.sync.aligned.m16n8k16.row.col.f32.bf16.bf16.f32 "
        "{%0,%1,%2,%3}, {%4,%5,%6,%7}, {%8,%9}, {%0,%1,%2,%3};\n"
        : "+f"(c[0]), "+f"(c[1]), "+f"(c[2]), "+f"(c[3])
        : "r"(a0), "r"(a1), "r"(a2), "r"(a3), "r"(b0), "r"(b1));
}

// ---------------- prep: degree count (+rank) fused with weight pre-split -------
__global__ void prep_kernel(const int* __restrict__ ei,
                            const float* __restrict__ b10, const float* __restrict__ b11,
                            const float* __restrict__ b20, const float* __restrict__ b21,
                            const float* __restrict__ b30, const float* __restrict__ b31) {
    int idx = blockIdx.x * blockDim.x + threadIdx.x;
    if (idx < ETOT) {
        int dst = (idx < NE) ? ei[NE + idx] : (idx - NE);
        g_rank[idx] = atomicAdd(&g_deg[dst], 1);
        return;
    }
    int i = idx - ETOT;
    if (i >= BTOT) return;
    const float* B; int M, local;
    if (i < OFF_L1_1)      { B = b10; M = 128; local = i; }
    else if (i < OFF_L2_0) { B = b11; M = 128; local = i - OFF_L1_1; }
    else if (i < OFF_L2_1) { B = b20; M = 64;  local = i - OFF_L2_0; }
    else if (i < OFF_L3_0) { B = b21; M = 64;  local = i - OFF_L2_1; }
    else if (i < OFF_L3_1) { B = b30; M = 32;  local = i - OFF_L3_0; }
    else                   { B = b31; M = 32;  local = i - OFF_L3_1; }
    int kp = local / M, n = local % M;
    float v0 = B[(size_t)(2 * kp) * M + n];
    float v1 = B[(size_t)(2 * kp + 1) * M + n];
    unsigned hi, lo;
    split_bf16x2(v0, v1, hi, lo);
    g_bh[i] = hi;
    g_bl[i] = lo;
}

// single-block exclusive scan (warp-shuffle based) + graph offsets + deg reset
__global__ void scan_kernel(const int* __restrict__ batch) {
    __shared__ int wsum[32];
    __shared__ int carry_s;
    int t = threadIdx.x, lane = t & 31, wid = t >> 5;
    if (t == 0) carry_s = 0;
    __syncthreads();
    for (int base = 0; base < NN; base += 1024) {
        int i = base + t;
        int v = (i < NN) ? g_deg[i] : 0;
        if (i < NN) g_deg[i] = 0;            // reset for next call
        int s = v;
#pragma unroll
        for (int o = 1; o < 32; o <<= 1) {
            int n = __shfl_up_sync(0xffffffffu, s, o);
            if (lane >= o) s += n;
        }
        if (lane == 31) wsum[wid] = s;
        __syncthreads();
        if (wid == 0) {
            int ws = wsum[lane];
#pragma unroll
            for (int o = 1; o < 32; o <<= 1) {
                int n = __shfl_up_sync(0xffffffffu, ws, o);
                if (lane >= o) ws += n;
            }
            wsum[lane] = ws;
        }
        __syncthreads();
        int carry = carry_s;
        int excl = carry + (wid ? wsum[wid - 1] : 0) + s - v;
        if (i < NN) g_off[i] = excl;
        int total = wsum[31];
        __syncthreads();
        if (t == 0) carry_s = carry + total;
        __syncthreads();
    }
    if (t == 0) g_off[NN] = carry_s;
    if (t <= NG) {
        if (t == NG) g_go[NG] = NN;
        else {
            int lo = 0, hi = NN;
            while (lo < hi) {
                int mid = (lo + hi) >> 1;
                if (batch[mid] < t) lo = mid + 1; else hi = mid;
            }
            g_go[t] = lo;
        }
    }
}

// ---------------- 3xBF16 tensor-core GEMM (A split at STS; fused GN; opt scatter)
// C[N,M] = A'[N,K] @ B[K,M] where A' = NORM ? relu((A - mus)*wr + gb) : A.
// SCAT: grid.z==2 slab performs the atomic-free edge scatter instead of GEMM.
template <bool NORM, bool SCAT>
__global__ __launch_bounds__(256) void gemm_bf16_dual(
    const float* __restrict__ A,
    int bOff0, int bOff1,
    float* __restrict__ Cp0, float* __restrict__ Cp1,
    int N, int K, int M,
    const float* __restrict__ gb, const int* __restrict__ batch,
    const int* __restrict__ ei) {
    if (SCAT && blockIdx.z == 2) {
        int nthr = gridDim.x * gridDim.y * 256;
        int id = (blockIdx.y * gridDim.x + blockIdx.x) * 256 + threadIdx.x;
        for (int e = id; e < ETOT; e += nthr) {
            int src, dst;
            if (e < NE) { src = ei[e]; dst = ei[NE + e]; }
            else        { src = dst = e - NE; }
            g_srcs[g_off[dst] + g_rank[e]] = src;
        }
        return;
    }
    int bOff = blockIdx.z ? bOff1 : bOff0;
    float* C = blockIdx.z ? Cp1 : Cp0;
    const unsigned* Bh = g_bh + bOff;
    const unsigned* Bl = g_bl + bOff;

    __shared__ unsigned Ash[2][8][136];  // [kpair][row], stride 136 (≡8 mod 32)
    __shared__ unsigned Asl[2][8][136];
    __shared__ unsigned Bsh[2][8][72];   // [kpair][col]
    __shared__ unsigned Bsl[2][8][72];

    int t = threadIdx.x;
    int w = t >> 5, lane = t & 31;
    int wr = w >> 1, wc = w & 1;         // 4x2 warp grid
    int grp = lane >> 2, tg = lane & 3;
    int row0 = blockIdx.y * 128;
    int col0 = blockIdx.x * 64;

    float c[2][4][4];
#pragma unroll
    for (int i = 0; i < 2; i++)
#pragma unroll
        for (int j = 0; j < 4; j++)
#pragma unroll
            for (int k = 0; k < 4; k++) c[i][j][k] = 0.f;

    float4 areg[2];

    auto lda_regs = [&](int kt) {
        int k0 = kt << 4;
#pragma unroll
        for (int u = 0; u < 2; u++) {
            int i = t + u * 256;
            int r = i >> 2, c4 = (i & 3) * 4;
            int gr = row0 + r;
            if (gr < N) {
                float4 a = *reinterpret_cast<const float4*>(A + (size_t)gr * K + k0 + c4);
                if (NORM) {
                    int g = batch[gr];
                    float4 mv = *reinterpret_cast<const float4*>(g_mus + (size_t)g * K + k0 + c4);
                    float4 wv = *reinterpret_cast<const float4*>(g_wr  + (size_t)g * K + k0 + c4);
                    float4 bv = *reinterpret_cast<const float4*>(gb + k0 + c4);
                    a.x = fmaxf(fmaf(a.x - mv.x, wv.x, bv.x), 0.f);
                    a.y = fmaxf(fmaf(a.y - mv.y, wv.y, bv.y), 0.f);
                    a.z = fmaxf(fmaf(a.z - mv.z, wv.z, bv.z), 0.f);
                    a.w = fmaxf(fmaf(a.w - mv.w, wv.w, bv.w), 0.f);
                }
                areg[u] = a;
            } else {
                areg[u] = make_float4(0.f, 0.f, 0.f, 0.f);
            }
        }
    };
    auto sts_a = [&](int stage) {
#pragma unroll
        for (int u = 0; u < 2; u++) {
            int i = t + u * 256;
            int r = i >> 2, kp = (i & 3) * 2;
            unsigned h0, l0, h1, l1;
            split_bf16x2(areg[u].x, areg[u].y, h0, l0);
            split_bf16x2(areg[u].z, areg[u].w, h1, l1);
            Ash[stage][kp][r] = h0; Ash[stage][kp + 1][r] = h1;
            Asl[stage][kp][r] = l0; Asl[stage][kp + 1][r] = l1;
        }
    };
    auto ldb_async = [&](int stage, int kt) {
        int buf = t >> 7;                // 0 = hi, 1 = lo
        int rem = t & 127;
        int r = rem >> 4, c4 = (rem & 15) * 4;
        bool p = (col0 + c4) < M;
        const unsigned* Bsel = buf ? Bl : Bh;
        const unsigned* src = p ? (Bsel + (size_t)(kt * 8 + r) * M + col0 + c4) : Bh;
        unsigned* dst = buf ? &Bsl[stage][r][c4] : &Bsh[stage][r][c4];
        cp_async16(dst, src, p);
    };

    int KT = K >> 4;
    lda_regs(0);
    ldb_async(0, 0);
    cp_commit();
    sts_a(0);

    for (int kt = 0; kt < KT; kt++) {
        int cur = kt & 1;
        if (kt + 1 < KT) {
            lda_regs(kt + 1);            // overlap LDG with compute below
            ldb_async(cur ^ 1, kt + 1);
            cp_commit();
            cp_wait<1>();
        } else {
            cp_wait<0>();
        }
        __syncthreads();                 // stage `cur` fully ready

        unsigned ah[2][4], al[2][4];
#pragma unroll
        for (int mt = 0; mt < 2; mt++) {
            int r0 = wr * 32 + mt * 16;
            ah[mt][0] = Ash[cur][tg][r0 + grp];
            ah[mt][1] = Ash[cur][tg][r0 + grp + 8];
            ah[mt][2] = Ash[cur][tg + 4][r0 + grp];
            ah[mt][3] = Ash[cur][tg + 4][r0 + grp + 8];
            al[mt][0] = Asl[cur][tg][r0 + grp];
            al[mt][1] = Asl[cur][tg][r0 + grp + 8];
            al[mt][2] = Asl[cur][tg + 4][r0 + grp];
            al[mt][3] = Asl[cur][tg + 4][r0 + grp + 8];
        }
#pragma unroll
        for (int nt = 0; nt < 4; nt++) {
            int ci = wc * 32 + nt * 8 + grp;
            unsigned bh0 = Bsh[cur][tg][ci];
            unsigned bh1 = Bsh[cur][tg + 4][ci];
            unsigned bl0 = Bsl[cur][tg][ci];
            unsigned bl1 = Bsl[cur][tg + 4][ci];
#pragma unroll
            for (int mt = 0; mt < 2; mt++) {
                mma_bf16(c[mt][nt], ah[mt][0], ah[mt][1], ah[mt][2], ah[mt][3], bh0, bh1);
                mma_bf16(c[mt][nt], al[mt][0], al[mt][1], al[mt][2], al[mt][3], bh0, bh1);
                mma_bf16(c[mt][nt], ah[mt][0], ah[mt][1], ah[mt][2], ah[mt][3], bl0, bl1);
            }
        }
        if (kt + 1 < KT) sts_a(cur ^ 1); // safe: stage cur^1 not read this iter
        __syncthreads();
    }

#pragma unroll
    for (int mt = 0; mt < 2; mt++) {
#pragma unroll
        for (int nt = 0; nt < 4; nt++) {
            int gc = col0 + wc * 32 + nt * 8 + 2 * tg;
            if (gc >= M) continue;
            int gr0 = row0 + wr * 32 + mt * 16 + grp;
            if (gr0 < N) {
                float2 v = make_float2(c[mt][nt][0], c[mt][nt][1]);
                *reinterpret_cast<float2*>(C + (size_t)gr0 * M + gc) = v;
            }
            int gr1 = gr0 + 8;
            if (gr1 < N) {
                float2 v = make_float2(c[mt][nt][2], c[mt][nt][3]);
                *reinterpret_cast<float2*>(C + (size_t)gr1 * M + gc) = v;
            }
        }
    }
}

// ---------------- GATv2: warp per dst node, online softmax, ping-pong 8-edge --
template <int V>
__device__ __forceinline__ void load_row(float* d, const float* p) {
    if (V == 4) {
        float4 t = *reinterpret_cast<const float4*>(p);
        d[0] = t.x; d[1] = t.y; d[V > 2 ? 2 : 0] = t.z; d[V > 3 ? 3 : 0] = t.w;
    } else if (V == 2) {
        float2 t = *reinterpret_cast<const float2*>(p);
        d[0] = t.x; d[V > 1 ? 1 : 0] = t.y;
    } else {
        d[0] = p[0];
    }
}

template <int V>
__device__ __forceinline__ float edge_score(const float* cur, const float* xrv,
                                            const float* attv) {
    float part = 0.f;
#pragma unroll
    for (int v = 0; v < V; v++) {
        float m = cur[v] + xrv[v];
        m = fmaxf(m, 0.2f * m);          // leaky relu (2 ops)
        part = fmaf(attv[v], m, part);
    }
    part += __shfl_xor_sync(0xffffffffu, part, 1);
    part += __shfl_xor_sync(0xffffffffu, part, 2);
    part += __shfl_xor_sync(0xffffffffu, part, 4);
    return part;
}

template <int C, bool MEAN>
__global__ void gat_kernel(const float* __restrict__ xl, const float* __restrict__ xr,
                           const float* __restrict__ att, const float* __restrict__ bias,
                           float* __restrict__ out) {
    constexpr int H = HEADS;
    constexpr int HC = H * C;
    constexpr int V = HC / 32;
    int warp = (blockIdx.x * blockDim.x + threadIdx.x) >> 5;
    int lane = threadIdx.x & 31;
    if (warp >= NN) return;
    int node = warp;

    float attv[V], xrv[V], acc[V];
#pragma unroll
    for (int v = 0; v < V; v++) {
        attv[v] = att[lane * V + v];
        xrv[v]  = xr[node * HC + lane * V + v];
        acc[v]  = 0.f;
    }
    float mrun = -CUDART_INF_F, lrun = 0.f;
    int beg = g_off[node], end = g_off[node + 1];
    const size_t lo = (size_t)lane * V;

    float p0[V], p1[V], p2[V], p3[V];
    float q0[V], q1[V], q2[V], q3[V];

    auto ldg = [&](float* d, int j_) {
        if (j_ < end) load_row<V>(d, xl + (size_t)g_srcs[j_] * HC + lo);
    };
    auto ldu = [&](float* d, int j_) {   // unguarded
        load_row<V>(d, xl + (size_t)g_srcs[j_] * HC + lo);
    };
    auto quad = [&](const float* a, const float* b, const float* cc, const float* d) {
        float e0 = edge_score<V>(a,  xrv, attv);
        float e1 = edge_score<V>(b,  xrv, attv);
        float e2 = edge_score<V>(cc, xrv, attv);
        float e3 = edge_score<V>(d,  xrv, attv);
        float nm = fmaxf(fmaxf(fmaxf(e0, e1), fmaxf(e2, e3)), mrun);
        float sc = __expf(mrun - nm);
        float w0 = __expf(e0 - nm);
        float w1 = __expf(e1 - nm);
        float w2 = __expf(e2 - nm);
        float w3 = __expf(e3 - nm);
#pragma unroll
        for (int v = 0; v < V; v++)
            acc[v] = fmaf(acc[v], sc,
                     fmaf(w0, a[v], fmaf(w1, b[v], fmaf(w2, cc[v], w3 * d[v]))));
        lrun = fmaf(lrun, sc, (w0 + w1) + (w2 + w3));
        mrun = nm;
    };
    auto single = [&](const float* pk) {
        float e = edge_score<V>(pk, xrv, attv);
        float nm = fmaxf(mrun, e);
        float sc = __expf(mrun - nm);
        float w  = __expf(e - nm);
#pragma unroll
        for (int v = 0; v < V; v++) acc[v] = fmaf(acc[v], sc, w * pk[v]);
        lrun = fmaf(lrun, sc, w);
        mrun = nm;
    };

    ldg(p0, beg); ldg(p1, beg + 1); ldg(p2, beg + 2); ldg(p3, beg + 3);

    int j = beg;
    for (; j + 8 <= end; j += 8) {
        ldu(q0, j + 4); ldu(q1, j + 5); ldu(q2, j + 6); ldu(q3, j + 7);
        quad(p0, p1, p2, p3);
        ldg(p0, j + 8); ldg(p1, j + 9); ldg(p2, j + 10); ldg(p3, j + 11);
        quad(q0, q1, q2, q3);
    }
    int rem = end - j;
    if (rem >= 4) {
        ldg(q0, j + 4); ldg(q1, j + 5); ldg(q2, j + 6);
        quad(p0, p1, p2, p3);
        if (rem > 4) single(q0);
        if (rem > 5) single(q1);
        if (rem > 6) single(q2);
    } else {
        if (rem > 0) single(p0);
        if (rem > 1) single(p1);
        if (rem > 2) single(p2);
    }

    float inv = 1.f / lrun;
    if (!MEAN) {
#pragma unroll
        for (int v = 0; v < V; v++)
            out[(size_t)node * HC + lane * V + v] = acc[v] * inv + bias[lane * V + v];
    } else {
        float r = acc[0] * inv;
        r += __shfl_xor_sync(0xffffffffu, r, 8);
        r += __shfl_xor_sync(0xffffffffu, r, 16);
        r *= 0.25f;
        if (lane < 8) out[(size_t)node * 8 + lane] = r + bias[lane];
    }
}

// ---------------- GraphNorm stats (normalize fused into consumers) ----------
template <int C>
__global__ void gn_part_kernel(const float* __restrict__ x) {
    constexpr int R = 256 / C;
    __shared__ float red[256], red2[256];
    int g = blockIdx.x, sub = blockIdx.y;
    int beg = g_go[g], end = g_go[g + 1];
    int t = threadIdx.x, c = t % C, r = t / C;
    float s = 0.f, q = 0.f;
    for (int i = beg + sub * R + r; i < end; i += NSUB * R) {
        float v = x[(size_t)i * C + c];
        s += v; q = fmaf(v, v, q);
    }
    red[t] = s; red2[t] = q;
    __syncthreads();
    if (t < C) {
        float ss = 0.f, qq = 0.f;
        for (int k = t; k < 256; k += C) { ss += red[k]; qq += red2[k]; }
        g_part[(g * NSUB + sub) * 2 * C + t] = ss;
        g_part[(g * NSUB + sub) * 2 * C + C + t] = qq;
    }
}

template <int C>
__global__ void gn_final_kernel(const float* __restrict__ w, const float* __restrict__ sc) {
    int g = blockIdx.x, c = threadIdx.x;
    int beg = g_go[g], end = g_go[g + 1];
    float cnt = fmaxf((float)(end - beg), 1.f);
    float s = 0.f, q = 0.f;
    for (int sub = 0; sub < NSUB; sub++) {
        s += g_part[(g * NSUB + sub) * 2 * C + c];
        q += g_part[(g * NSUB + sub) * 2 * C + C + c];
    }
    float mu = s / cnt;
    float mus = mu * sc[c];
    float var = q / cnt - 2.f * mus * mu + mus * mus;
    g_mus[g * C + c] = mus;
    g_wr[g * C + c] = w[c] * rsqrtf(var + 1e-5f);
}

// ---------------- pool + linear (gn3 normalize+relu fused in) ----------------
__global__ void pool_linear_kernel(const float* __restrict__ h, const float* __restrict__ gb,
                                   const float* __restrict__ lw, const float* __restrict__ lb,
                                   float* __restrict__ out) {
    __shared__ float red[256];
    __shared__ float feat[8];
    int g = blockIdx.x;
    int beg = g_go[g], end = g_go[g + 1];
    float fcnt = fmaxf((float)(end - beg), 1.f);
    int t = threadIdx.x;
    int c = t & 7, r = t >> 3;
    float mus = g_mus[g * 8 + c];
    float wrc = g_wr[g * 8 + c];
    float bc  = gb[c];
    float sum = 0.f;
    for (int i = beg + r; i < end; i += 32) {
        float val = fmaxf(fmaf(h[(size_t)i * 8 + c] - mus, wrc, bc), 0.f);
        sum += val;
    }
    red[t] = sum; __syncthreads();
    if (t < 8) { float v = 0.f; for (int k = t; k < 256; k += 8) v += red[k]; feat[t] = v / fcnt; }
    __syncthreads();
    if (t < 8) out[NG * 4 + g * 8 + t] = feat[t];   // features after logits block
    if (t < 4) {
        float v = lb[t];
#pragma unroll
        for (int c2 = 0; c2 < 8; c2++) v = fmaf(feat[c2], lw[c2 * 4 + t], v);
        out[g * 4 + t] = v;                          // logits
    }
}

// ---------------- host orchestration ----------------
template <bool NORM, bool SCAT>
static void launch_gemm_dual(const float* A, int bOff0, int bOff1,
                             float* C0, float* C1, int N, int K, int M,
                             const float* gb, const int* batch, const int* ei) {
    dim3 grid((M + 63) / 64, (N + 127) / 128, SCAT ? 3 : 2);
    gemm_bf16_dual<NORM, SCAT><<<grid, 256>>>(A, bOff0, bOff1, C0, C1, N, K, M,
                                              gb, batch, ei);
}

extern "C" void kernel_launch(void* const* d_in, const int* in_sizes, int n_in,
                              void* d_out, int out_size) {
    const float* x     = (const float*)d_in[0];
    const int*   ei    = (const int*)d_in[1];
    const int*   batch = (const int*)d_in[2];
    const float* w_l1 = (const float*)d_in[3];
    const float* w_r1 = (const float*)d_in[4];
    const float* att1 = (const float*)d_in[5];
    const float* b1   = (const float*)d_in[6];
    const float* gn1w = (const float*)d_in[7];
    const float* gn1b = (const float*)d_in[8];
    const float* gn1s = (const float*)d_in[9];
    const float* w_l2 = (const float*)d_in[10];
    const float* w_r2 = (const float*)d_in[11];
    const float* att2 = (const float*)d_in[12];
    const float* b2   = (const float*)d_in[13];
    const float* gn2w = (const float*)d_in[14];
    const float* gn2b = (const float*)d_in[15];
    const float* gn2s = (const float*)d_in[16];
    const float* w_l3 = (const float*)d_in[17];
    const float* w_r3 = (const float*)d_in[18];
    const float* att3 = (const float*)d_in[19];
    const float* b3   = (const float*)d_in[20];
    const float* gn3w = (const float*)d_in[21];
    const float* gn3b = (const float*)d_in[22];
    const float* gn3s = (const float*)d_in[23];
    const float* linw = (const float*)d_in[24];
    const float* linb = (const float*)d_in[25];
    float* out = (float*)d_out;

    float *xl, *xr, *h1, *h2, *h3;
    cudaGetSymbolAddress((void**)&xl, g_xl);
    cudaGetSymbolAddress((void**)&xr, g_xr);
    cudaGetSymbolAddress((void**)&h1, g_h1);
    cudaGetSymbolAddress((void**)&h2, g_h2);
    cudaGetSymbolAddress((void**)&h3, g_h3);

    const int GAT_BLOCKS = (NN * 32 + 255) / 256;

    // #0: degree count (+ranks) fused with weight pre-split
    prep_kernel<<<(ETOT + BTOT + 255) / 256, 256>>>(ei, w_l1, w_r1, w_l2, w_r2,
                                                    w_l3, w_r3);
    // #1: scan + graph offsets + deg reset
    scan_kernel<<<1, 1024>>>(batch);
    // #2: layer-1 GEMM with fused atomic-free scatter (z==2 slab)
    launch_gemm_dual<false, true>(x, OFF_L1_0, OFF_L1_1, xl, xr,
                                  NN, 128, 128, nullptr, nullptr, ei);
    // #3: GAT layer 1  (ncu capture slot)
    gat_kernel<32, false><<<GAT_BLOCKS, 256>>>(xl, xr, att1, b1, h1);
    gn_part_kernel<128><<<dim3(NG, NSUB), 256>>>(h1);
    gn_final_kernel<128><<<NG, 128>>>(gn1w, gn1s);

    // layer 2: 128 -> 4x16 concat = 64 (GN of h1 fused into A-load)
    launch_gemm_dual<true, false>(h1, OFF_L2_0, OFF_L2_1, xl, xr,
                                  NN, 128, 64, gn1b, batch, nullptr);
    gat_kernel<16, false><<<GAT_BLOCKS, 256>>>(xl, xr, att2, b2, h2);
    gn_part_kernel<64><<<dim3(NG, NSUB), 256>>>(h2);
    gn_final_kernel<64><<<NG, 64>>>(gn2w, gn2s);

    // layer 3: 64 -> 4x8 mean = 8 (GN of h2 fused into A-load)
    launch_gemm_dual<true, false>(h2, OFF_L3_0, OFF_L3_1, xl, xr,
                                  NN, 64, 32, gn2b, batch, nullptr);
    gat_kernel<8, true><<<GAT_BLOCKS, 256>>>(xl, xr, att3, b3, h3);
    gn_part_kernel<8><<<dim3(NG, NSUB), 256>>>(h3);
    gn_final_kernel<8><<<NG, 8>>>(gn3w, gn3s);

    // pool + linear (gn3 normalize+relu fused): out[0:256] logits, out[256:768] features
    pool_linear_kernel<<<NG, 256>>>(h3, gn3b, linw, linb, out);
}

// round 14
// speedup vs baseline: 1.0196x; 1.0196x over previous
#include <cuda_runtime.h>
#include <cuda_bf16.h>
#include <math_constants.h>

// Problem constants (fixed by the dataset)
#define NN 50000
#define NE 800000
#define ETOT (NE + NN)       // edges + self loops = 850000
#define NG 64
#define HEADS 4
#define NSUB 8               // GraphNorm sub-partitions per graph

// ---------------- scratch (no cudaMalloc allowed) ----------------
__device__ float g_xl[NN * 128];
__device__ float g_xr[NN * 128];
__device__ float g_h1[NN * 128];
__device__ float g_h2[NN * 64];
__device__ float g_h3[NN * 8];
__device__ int   g_deg[NN];      // zero-init at load; re-zeroed inside scan each call
__device__ int   g_off[NN + 1];
__device__ int   g_rank[ETOT];   // per-edge arrival rank at its dst
__device__ int   g_srcs[ETOT];
__device__ int   g_go[NG + 1];
__device__ float g_part[NG * NSUB * 2 * 128];
__device__ float g_mus[NG * 128];
__device__ float g_wr[NG * 128];

// packed bf16x2 hi/lo weight buffers (k-pairs x M), all 6 matrices
#define OFF_L1_0 0
#define OFF_L1_1 8192
#define OFF_L2_0 16384
#define OFF_L2_1 20480
#define OFF_L3_0 24576
#define OFF_L3_1 25600
#define BTOT 26624
__device__ unsigned g_bh[BTOT];
__device__ unsigned g_bl[BTOT];

// ---------------- cp.async helpers ----------------
__device__ __forceinline__ void cp_async16(void* smem_ptr, const void* gmem_ptr, bool pred) {
    unsigned saddr = (unsigned)__cvta_generic_to_shared(smem_ptr);
    int sz = pred ? 16 : 0;
    asm volatile("cp.async.ca.shared.global [%0], [%1], 16, %2;\n"
                 :: "r"(saddr), "l"(gmem_ptr), "r"(sz));
}
__device__ __forceinline__ void cp_commit() { asm volatile("cp.async.commit_group;\n"); }
template <int N>
__device__ __forceinline__ void cp_wait() { asm volatile("cp.async.wait_group %0;\n" :: "n"(N)); }

// ---------------- bf16 split helpers ----------------
__device__ __forceinline__ void split_bf16x2(float v0, float v1, unsigned& hi, unsigned& lo) {
    asm("cvt.rn.bf16x2.f32 %0, %1, %2;" : "=r"(hi) : "f"(v1), "f"(v0));
    float f0 = __uint_as_float(hi << 16);
    float f1 = __uint_as_float(hi & 0xffff0000u);
    asm("cvt.rn.bf16x2.f32 %0, %1, %2;" : "=r"(lo) : "f"(v1 - f1), "f"(v0 - f0));
}

__device__ __forceinline__ void mma_bf16(float c[4], unsigned a0, unsigned a1,
                                         unsigned a2, unsigned a3,
                                         unsigned b0, unsigned b1) {
    asm volatile(
        "mma.sync.aligned.m16n8k16.row.col.f32.bf16.bf16.f32 "
        "{%0,%1,%2,%3}, {%4,%5,%6,%7}, {%8,%9}, {%0,%1,%2,%3};\n"
        : "+f"(c[0]), "+f"(c[1]), "+f"(c[2]), "+f"(c[3])
        : "r"(a0), "r"(a1), "r"(a2), "r"(a3), "r"(b0), "r"(b1));
}

// ---------------- prep: degree count (+rank) fused with weight pre-split -------
__global__ void prep_kernel(const int* __restrict__ ei,
                            const float* __restrict__ b10, const float* __restrict__ b11,
                            const float* __restrict__ b20, const float* __restrict__ b21,
                            const float* __restrict__ b30, const float* __restrict__ b31) {
    int idx = blockIdx.x * blockDim.x + threadIdx.x;
    if (idx < ETOT) {
        int dst = (idx < NE) ? ei[NE + idx] : (idx - NE);
        g_rank[idx] = atomicAdd(&g_deg[dst], 1);
        return;
    }
    int i = idx - ETOT;
    if (i >= BTOT) return;
    const float* B; int M, local;
    if (i < OFF_L1_1)      { B = b10; M = 128; local = i; }
    else if (i < OFF_L2_0) { B = b11; M = 128; local = i - OFF_L1_1; }
    else if (i < OFF_L2_1) { B = b20; M = 64;  local = i - OFF_L2_0; }
    else if (i < OFF_L3_0) { B = b21; M = 64;  local = i - OFF_L2_1; }
    else if (i < OFF_L3_1) { B = b30; M = 32;  local = i - OFF_L3_0; }
    else                   { B = b31; M = 32;  local = i - OFF_L3_1; }
    int kp = local / M, n = local % M;
    float v0 = B[(size_t)(2 * kp) * M + n];
    float v1 = B[(size_t)(2 * kp + 1) * M + n];
    unsigned hi, lo;
    split_bf16x2(v0, v1, hi, lo);
    g_bh[i] = hi;
    g_bl[i] = lo;
}

// single-block exclusive scan (warp-shuffle based) + graph offsets + deg reset
__global__ void scan_kernel(const int* __restrict__ batch) {
    __shared__ int wsum[32];
    __shared__ int carry_s;
    int t = threadIdx.x, lane = t & 31, wid = t >> 5;
    if (t == 0) carry_s = 0;
    __syncthreads();
    for (int base = 0; base < NN; base += 1024) {
        int i = base + t;
        int v = (i < NN) ? g_deg[i] : 0;
        if (i < NN) g_deg[i] = 0;            // reset for next call
        int s = v;
#pragma unroll
        for (int o = 1; o < 32; o <<= 1) {
            int n = __shfl_up_sync(0xffffffffu, s, o);
            if (lane >= o) s += n;
        }
        if (lane == 31) wsum[wid] = s;
        __syncthreads();
        if (wid == 0) {
            int ws = wsum[lane];
#pragma unroll
            for (int o = 1; o < 32; o <<= 1) {
                int n = __shfl_up_sync(0xffffffffu, ws, o);
                if (lane >= o) ws += n;
            }
            wsum[lane] = ws;
        }
        __syncthreads();
        int carry = carry_s;
        int excl = carry + (wid ? wsum[wid - 1] : 0) + s - v;
        if (i < NN) g_off[i] = excl;
        int total = wsum[31];
        __syncthreads();
        if (t == 0) carry_s = carry + total;
        __syncthreads();
    }
    if (t == 0) g_off[NN] = carry_s;
    if (t <= NG) {
        if (t == NG) g_go[NG] = NN;
        else {
            int lo = 0, hi = NN;
            while (lo < hi) {
                int mid = (lo + hi) >> 1;
                if (batch[mid] < t) lo = mid + 1; else hi = mid;
            }
            g_go[t] = lo;
        }
    }
}

// atomic-free scatter via precomputed ranks
__global__ void scatter_kernel(const int* __restrict__ ei) {
    int e = blockIdx.x * blockDim.x + threadIdx.x;
    if (e >= ETOT) return;
    int src, dst;
    if (e < NE) { src = ei[e]; dst = ei[NE + e]; }
    else        { src = dst = e - NE; }
    g_srcs[g_off[dst] + g_rank[e]] = src;
}

// ---------------- 3xBF16 tensor-core GEMM (A split at STS; optional fused GN) --
// C[N,M] = A'[N,K] @ B[K,M] where A' = NORM ? relu((A - mus)*wr + gb) : A.
template <bool NORM>
__global__ __launch_bounds__(256) void gemm_bf16_dual(
    const float* __restrict__ A,
    int bOff0, int bOff1,
    float* __restrict__ Cp0, float* __restrict__ Cp1,
    int N, int K, int M,
    const float* __restrict__ gb, const int* __restrict__ batch) {
    int bOff = blockIdx.z ? bOff1 : bOff0;
    float* C = blockIdx.z ? Cp1 : Cp0;
    const unsigned* Bh = g_bh + bOff;
    const unsigned* Bl = g_bl + bOff;

    __shared__ unsigned Ash[2][8][136];  // [kpair][row], stride 136 (≡8 mod 32)
    __shared__ unsigned Asl[2][8][136];
    __shared__ unsigned Bsh[2][8][72];   // [kpair][col]
    __shared__ unsigned Bsl[2][8][72];

    int t = threadIdx.x;
    int w = t >> 5, lane = t & 31;
    int wr = w >> 1, wc = w & 1;         // 4x2 warp grid
    int grp = lane >> 2, tg = lane & 3;
    int row0 = blockIdx.y * 128;
    int col0 = blockIdx.x * 64;

    float c[2][4][4];
#pragma unroll
    for (int i = 0; i < 2; i++)
#pragma unroll
        for (int j = 0; j < 4; j++)
#pragma unroll
            for (int k = 0; k < 4; k++) c[i][j][k] = 0.f;

    float4 areg[2];

    auto lda_regs = [&](int kt) {
        int k0 = kt << 4;
#pragma unroll
        for (int u = 0; u < 2; u++) {
            int i = t + u * 256;
            int r = i >> 2, c4 = (i & 3) * 4;
            int gr = row0 + r;
            if (gr < N) {
                float4 a = *reinterpret_cast<const float4*>(A + (size_t)gr * K + k0 + c4);
                if (NORM) {
                    int g = batch[gr];
                    float4 mv = *reinterpret_cast<const float4*>(g_mus + (size_t)g * K + k0 + c4);
                    float4 wv = *reinterpret_cast<const float4*>(g_wr  + (size_t)g * K + k0 + c4);
                    float4 bv = *reinterpret_cast<const float4*>(gb + k0 + c4);
                    a.x = fmaxf(fmaf(a.x - mv.x, wv.x, bv.x), 0.f);
                    a.y = fmaxf(fmaf(a.y - mv.y, wv.y, bv.y), 0.f);
                    a.z = fmaxf(fmaf(a.z - mv.z, wv.z, bv.z), 0.f);
                    a.w = fmaxf(fmaf(a.w - mv.w, wv.w, bv.w), 0.f);
                }
                areg[u] = a;
            } else {
                areg[u] = make_float4(0.f, 0.f, 0.f, 0.f);
            }
        }
    };
    auto sts_a = [&](int stage) {
#pragma unroll
        for (int u = 0; u < 2; u++) {
            int i = t + u * 256;
            int r = i >> 2, kp = (i & 3) * 2;
            unsigned h0, l0, h1, l1;
            split_bf16x2(areg[u].x, areg[u].y, h0, l0);
            split_bf16x2(areg[u].z, areg[u].w, h1, l1);
            Ash[stage][kp][r] = h0; Ash[stage][kp + 1][r] = h1;
            Asl[stage][kp][r] = l0; Asl[stage][kp + 1][r] = l1;
        }
    };
    auto ldb_async = [&](int stage, int kt) {
        int buf = t >> 7;                // 0 = hi, 1 = lo
        int rem = t & 127;
        int r = rem >> 4, c4 = (rem & 15) * 4;
        bool p = (col0 + c4) < M;
        const unsigned* Bsel = buf ? Bl : Bh;
        const unsigned* src = p ? (Bsel + (size_t)(kt * 8 + r) * M + col0 + c4) : Bh;
        unsigned* dst = buf ? &Bsl[stage][r][c4] : &Bsh[stage][r][c4];
        cp_async16(dst, src, p);
    };

    int KT = K >> 4;
    lda_regs(0);
    ldb_async(0, 0);
    cp_commit();
    sts_a(0);

    for (int kt = 0; kt < KT; kt++) {
        int cur = kt & 1;
        if (kt + 1 < KT) {
            lda_regs(kt + 1);            // overlap LDG with compute below
            ldb_async(cur ^ 1, kt + 1);
            cp_commit();
            cp_wait<1>();
        } else {
            cp_wait<0>();
        }
        __syncthreads();                 // stage `cur` fully ready

        unsigned ah[2][4], al[2][4];
#pragma unroll
        for (int mt = 0; mt < 2; mt++) {
            int r0 = wr * 32 + mt * 16;
            ah[mt][0] = Ash[cur][tg][r0 + grp];
            ah[mt][1] = Ash[cur][tg][r0 + grp + 8];
            ah[mt][2] = Ash[cur][tg + 4][r0 + grp];
            ah[mt][3] = Ash[cur][tg + 4][r0 + grp + 8];
            al[mt][0] = Asl[cur][tg][r0 + grp];
            al[mt][1] = Asl[cur][tg][r0 + grp + 8];
            al[mt][2] = Asl[cur][tg + 4][r0 + grp];
            al[mt][3] = Asl[cur][tg + 4][r0 + grp + 8];
        }
#pragma unroll
        for (int nt = 0; nt < 4; nt++) {
            int ci = wc * 32 + nt * 8 + grp;
            unsigned bh0 = Bsh[cur][tg][ci];
            unsigned bh1 = Bsh[cur][tg + 4][ci];
            unsigned bl0 = Bsl[cur][tg][ci];
            unsigned bl1 = Bsl[cur][tg + 4][ci];
#pragma unroll
            for (int mt = 0; mt < 2; mt++) {
                mma_bf16(c[mt][nt], ah[mt][0], ah[mt][1], ah[mt][2], ah[mt][3], bh0, bh1);
                mma_bf16(c[mt][nt], al[mt][0], al[mt][1], al[mt][2], al[mt][3], bh0, bh1);
                mma_bf16(c[mt][nt], ah[mt][0], ah[mt][1], ah[mt][2], ah[mt][3], bl0, bl1);
            }
        }
        if (kt + 1 < KT) sts_a(cur ^ 1); // safe: stage cur^1 not read this iter
        __syncthreads();
    }

#pragma unroll
    for (int mt = 0; mt < 2; mt++) {
#pragma unroll
        for (int nt = 0; nt < 4; nt++) {
            int gc = col0 + wc * 32 + nt * 8 + 2 * tg;
            if (gc >= M) continue;
            int gr0 = row0 + wr * 32 + mt * 16 + grp;
            if (gr0 < N) {
                float2 v = make_float2(c[mt][nt][0], c[mt][nt][1]);
                *reinterpret_cast<float2*>(C + (size_t)gr0 * M + gc) = v;
            }
            int gr1 = gr0 + 8;
            if (gr1 < N) {
                float2 v = make_float2(c[mt][nt][2], c[mt][nt][3]);
                *reinterpret_cast<float2*>(C + (size_t)gr1 * M + gc) = v;
            }
        }
    }
}

// ---------------- GATv2: warp per dst node, online softmax, 4-edge unroll ----
// (round-10 measured body; __launch_bounds__(256,4) = occupancy experiment)
template <int V>
__device__ __forceinline__ void load_row(float* d, const float* p) {
    if (V == 4) {
        float4 t = *reinterpret_cast<const float4*>(p);
        d[0] = t.x; d[1] = t.y; d[V > 2 ? 2 : 0] = t.z; d[V > 3 ? 3 : 0] = t.w;
    } else if (V == 2) {
        float2 t = *reinterpret_cast<const float2*>(p);
        d[0] = t.x; d[V > 1 ? 1 : 0] = t.y;
    } else {
        d[0] = p[0];
    }
}

template <int V>
__device__ __forceinline__ float edge_score(const float* cur, const float* xrv,
                                            const float* attv) {
    float part = 0.f;
#pragma unroll
    for (int v = 0; v < V; v++) {
        float m = cur[v] + xrv[v];
        m = fmaxf(m, 0.2f * m);          // leaky relu
        part = fmaf(attv[v], m, part);
    }
    part += __shfl_xor_sync(0xffffffffu, part, 1);
    part += __shfl_xor_sync(0xffffffffu, part, 2);
    part += __shfl_xor_sync(0xffffffffu, part, 4);
    return part;
}

template <int C, bool MEAN>
__global__ void __launch_bounds__(256, 4)
gat_kernel(const float* __restrict__ xl, const float* __restrict__ xr,
           const float* __restrict__ att, const float* __restrict__ bias,
           float* __restrict__ out) {
    constexpr int H = HEADS;
    constexpr int HC = H * C;
    constexpr int V = HC / 32;
    int warp = (blockIdx.x * blockDim.x + threadIdx.x) >> 5;
    int lane = threadIdx.x & 31;
    if (warp >= NN) return;
    int node = warp;

    float attv[V], xrv[V], acc[V];
#pragma unroll
    for (int v = 0; v < V; v++) {
        attv[v] = att[lane * V + v];
        xrv[v]  = xr[node * HC + lane * V + v];
        acc[v]  = 0.f;
    }
    float mrun = -CUDART_INF_F, lrun = 0.f;
    int beg = g_off[node], end = g_off[node + 1];
    const size_t lo = (size_t)lane * V;

    float p0[V], p1[V], p2[V], p3[V];
    load_row<V>(p0, xl + (size_t)g_srcs[beg] * HC + lo);
    if (beg + 1 < end) load_row<V>(p1, xl + (size_t)g_srcs[beg + 1] * HC + lo);
    if (beg + 2 < end) load_row<V>(p2, xl + (size_t)g_srcs[beg + 2] * HC + lo);
    if (beg + 3 < end) load_row<V>(p3, xl + (size_t)g_srcs[beg + 3] * HC + lo);

    auto single = [&](const float* pk) {
        float e = edge_score<V>(pk, xrv, attv);
        float nm = fmaxf(mrun, e);
        float sc = __expf(mrun - nm);
        float w  = __expf(e - nm);
#pragma unroll
        for (int v = 0; v < V; v++) acc[v] = fmaf(acc[v], sc, w * pk[v]);
        lrun = fmaf(lrun, sc, w);
        mrun = nm;
    };

    int j = beg;
    for (; j + 4 <= end; j += 4) {
        float c0[V], c1[V], c2[V], c3[V];
#pragma unroll
        for (int v = 0; v < V; v++) {
            c0[v] = p0[v]; c1[v] = p1[v]; c2[v] = p2[v]; c3[v] = p3[v];
        }
        if (j + 4 < end) load_row<V>(p0, xl + (size_t)g_srcs[j + 4] * HC + lo);
        if (j + 5 < end) load_row<V>(p1, xl + (size_t)g_srcs[j + 5] * HC + lo);
        if (j + 6 < end) load_row<V>(p2, xl + (size_t)g_srcs[j + 6] * HC + lo);
        if (j + 7 < end) load_row<V>(p3, xl + (size_t)g_srcs[j + 7] * HC + lo);

        float e0 = edge_score<V>(c0, xrv, attv);
        float e1 = edge_score<V>(c1, xrv, attv);
        float e2 = edge_score<V>(c2, xrv, attv);
        float e3 = edge_score<V>(c3, xrv, attv);
        float nm = fmaxf(fmaxf(fmaxf(e0, e1), fmaxf(e2, e3)), mrun);
        float sc = __expf(mrun - nm);
        float w0 = __expf(e0 - nm);
        float w1 = __expf(e1 - nm);
        float w2 = __expf(e2 - nm);
        float w3 = __expf(e3 - nm);
#pragma unroll
        for (int v = 0; v < V; v++)
            acc[v] = fmaf(acc[v], sc,
                     fmaf(w0, c0[v], fmaf(w1, c1[v], fmaf(w2, c2[v], w3 * c3[v]))));
        lrun = fmaf(lrun, sc, (w0 + w1) + (w2 + w3));
        mrun = nm;
    }
    // tail 0..3 edges live in p0..p2
    if (j < end)     single(p0);
    if (j + 1 < end) single(p1);
    if (j + 2 < end) single(p2);

    float inv = 1.f / lrun;
    if (!MEAN) {
#pragma unroll
        for (int v = 0; v < V; v++)
            out[(size_t)node * HC + lane * V + v] = acc[v] * inv + bias[lane * V + v];
    } else {
        float r = acc[0] * inv;
        r += __shfl_xor_sync(0xffffffffu, r, 8);
        r += __shfl_xor_sync(0xffffffffu, r, 16);
        r *= 0.25f;
        if (lane < 8) out[(size_t)node * 8 + lane] = r + bias[lane];
    }
}

// ---------------- GraphNorm stats (normalize fused into consumers) ----------
template <int C>
__global__ void gn_part_kernel(const float* __restrict__ x) {
    constexpr int R = 256 / C;
    __shared__ float red[256], red2[256];
    int g = blockIdx.x, sub = blockIdx.y;
    int beg = g_go[g], end = g_go[g + 1];
    int t = threadIdx.x, c = t % C, r = t / C;
    float s = 0.f, q = 0.f;
    for (int i = beg + sub * R + r; i < end; i += NSUB * R) {
        float v = x[(size_t)i * C + c];
        s += v; q = fmaf(v, v, q);
    }
    red[t] = s; red2[t] = q;
    __syncthreads();
    if (t < C) {
        float ss = 0.f, qq = 0.f;
        for (int k = t; k < 256; k += C) { ss += red[k]; qq += red2[k]; }
        g_part[(g * NSUB + sub) * 2 * C + t] = ss;
        g_part[(g * NSUB + sub) * 2 * C + C + t] = qq;
    }
}

template <int C>
__global__ void gn_final_kernel(const float* __restrict__ w, const float* __restrict__ sc) {
    int g = blockIdx.x, c = threadIdx.x;
    int beg = g_go[g], end = g_go[g + 1];
    float cnt = fmaxf((float)(end - beg), 1.f);
    float s = 0.f, q = 0.f;
    for (int sub = 0; sub < NSUB; sub++) {
        s += g_part[(g * NSUB + sub) * 2 * C + c];
        q += g_part[(g * NSUB + sub) * 2 * C + C + c];
    }
    float mu = s / cnt;
    float mus = mu * sc[c];
    float var = q / cnt - 2.f * mus * mu + mus * mus;
    g_mus[g * C + c] = mus;
    g_wr[g * C + c] = w[c] * rsqrtf(var + 1e-5f);
}

// ---------------- pool + linear (gn3 normalize+relu fused in) ----------------
__global__ void pool_linear_kernel(const float* __restrict__ h, const float* __restrict__ gb,
                                   const float* __restrict__ lw, const float* __restrict__ lb,
                                   float* __restrict__ out) {
    __shared__ float red[256];
    __shared__ float feat[8];
    int g = blockIdx.x;
    int beg = g_go[g], end = g_go[g + 1];
    float fcnt = fmaxf((float)(end - beg), 1.f);
    int t = threadIdx.x;
    int c = t & 7, r = t >> 3;
    float mus = g_mus[g * 8 + c];
    float wrc = g_wr[g * 8 + c];
    float bc  = gb[c];
    float sum = 0.f;
    for (int i = beg + r; i < end; i += 32) {
        float val = fmaxf(fmaf(h[(size_t)i * 8 + c] - mus, wrc, bc), 0.f);
        sum += val;
    }
    red[t] = sum; __syncthreads();
    if (t < 8) { float v = 0.f; for (int k = t; k < 256; k += 8) v += red[k]; feat[t] = v / fcnt; }
    __syncthreads();
    if (t < 8) out[NG * 4 + g * 8 + t] = feat[t];   // features after logits block
    if (t < 4) {
        float v = lb[t];
#pragma unroll
        for (int c2 = 0; c2 < 8; c2++) v = fmaf(feat[c2], lw[c2 * 4 + t], v);
        out[g * 4 + t] = v;                          // logits
    }
}

// ---------------- host orchestration ----------------
template <bool NORM>
static void launch_gemm_dual(const float* A, int bOff0, int bOff1,
                             float* C0, float* C1, int N, int K, int M,
                             const float* gb, const int* batch) {
    dim3 grid((M + 63) / 64, (N + 127) / 128, 2);
    gemm_bf16_dual<NORM><<<grid, 256>>>(A, bOff0, bOff1, C0, C1, N, K, M, gb, batch);
}

extern "C" void kernel_launch(void* const* d_in, const int* in_sizes, int n_in,
                              void* d_out, int out_size) {
    const float* x     = (const float*)d_in[0];
    const int*   ei    = (const int*)d_in[1];
    const int*   batch = (const int*)d_in[2];
    const float* w_l1 = (const float*)d_in[3];
    const float* w_r1 = (const float*)d_in[4];
    const float* att1 = (const float*)d_in[5];
    const float* b1   = (const float*)d_in[6];
    const float* gn1w = (const float*)d_in[7];
    const float* gn1b = (const float*)d_in[8];
    const float* gn1s = (const float*)d_in[9];
    const float* w_l2 = (const float*)d_in[10];
    const float* w_r2 = (const float*)d_in[11];
    const float* att2 = (const float*)d_in[12];
    const float* b2   = (const float*)d_in[13];
    const float* gn2w = (const float*)d_in[14];
    const float* gn2b = (const float*)d_in[15];
    const float* gn2s = (const float*)d_in[16];
    const float* w_l3 = (const float*)d_in[17];
    const float* w_r3 = (const float*)d_in[18];
    const float* att3 = (const float*)d_in[19];
    const float* b3   = (const float*)d_in[20];
    const float* gn3w = (const float*)d_in[21];
    const float* gn3b = (const float*)d_in[22];
    const float* gn3s = (const float*)d_in[23];
    const float* linw = (const float*)d_in[24];
    const float* linb = (const float*)d_in[25];
    float* out = (float*)d_out;

    float *xl, *xr, *h1, *h2, *h3;
    cudaGetSymbolAddress((void**)&xl, g_xl);
    cudaGetSymbolAddress((void**)&xr, g_xr);
    cudaGetSymbolAddress((void**)&h1, g_h1);
    cudaGetSymbolAddress((void**)&h2, g_h2);
    cudaGetSymbolAddress((void**)&h3, g_h3);

    const int GAT_BLOCKS = (NN * 32 + 255) / 256;

    // #0: degree count (+ranks) fused with weight pre-split
    prep_kernel<<<(ETOT + BTOT + 255) / 256, 256>>>(ei, w_l1, w_r1, w_l2, w_r2,
                                                    w_l3, w_r3);
    // #1: scan + graph offsets + deg reset
    scan_kernel<<<1, 1024>>>(batch);
    // #2: atomic-free scatter
    scatter_kernel<<<(ETOT + 255) / 256, 256>>>(ei);
    // #3: layer-1 GEMM  (ncu capture slot — verify it's back to ~47us)
    launch_gemm_dual<false>(x, OFF_L1_0, OFF_L1_1, xl, xr,
                            NN, 128, 128, nullptr, nullptr);

    // layer 1: 128 -> 4x32 concat = 128
    gat_kernel<32, false><<<GAT_BLOCKS, 256>>>(xl, xr, att1, b1, h1);
    gn_part_kernel<128><<<dim3(NG, NSUB), 256>>>(h1);
    gn_final_kernel<128><<<NG, 128>>>(gn1w, gn1s);

    // layer 2: 128 -> 4x16 concat = 64 (GN of h1 fused into A-load)
    launch_gemm_dual<true>(h1, OFF_L2_0, OFF_L2_1, xl, xr,
                           NN, 128, 64, gn1b, batch);
    gat_kernel<16, false><<<GAT_BLOCKS, 256>>>(xl, xr, att2, b2, h2);
    gn_part_kernel<64><<<dim3(NG, NSUB), 256>>>(h2);
    gn_final_kernel<64><<<NG, 64>>>(gn2w, gn2s);

    // layer 3: 64 -> 4x8 mean = 8 (GN of h2 fused into A-load)
    launch_gemm_dual<true>(h2, OFF_L3_0, OFF_L3_1, xl, xr,
                           NN, 64, 32, gn2b, batch);
    gat_kernel<8, true><<<GAT_BLOCKS, 256>>>(xl, xr, att3, b3, h3);
    gn_part_kernel<8><<<dim3(NG, NSUB), 256>>>(h3);
    gn_final_kernel<8><<<NG, 8>>>(gn3w, gn3s);

    // pool + linear (gn3 normalize+relu fused): out[0:256] logits, out[256:768] features
    pool_linear_kernel<<<NG, 256>>>(h3, gn3b, linw, linb, out);
}